// round 16
// baseline (speedup 1.0000x reference)
#include <cuda_runtime.h>
#include <cuda_fp16.h>

// SimpleGRU: B=2048, T=2048, H=32, scalar input.
// R16: warp-level tensor cores, TWO independent instances per warp
// (16 batches). Each instance: preacts via mma.m16n8k16 (A = W_hh
// stationary, shared by both instances; B = h, n=8 batches; fp32
// accumulate, biases in C). The two instances' serial chains
// (shfl/prmt -> 12 HMMA -> cvt -> fp16 tail) hide each other's latency.
// Thread map per instance: gid = tid>>2 (0..7) = unit row, tig = tid&3;
// thread holds units {gid+8j} x batches {2tig, 2tig+1}.

#define FULL_MASK 0xffffffffu

__device__ __forceinline__ __half2 htanh2(__half2 a) {
    unsigned int d, s = *reinterpret_cast<unsigned int*>(&a);
    asm("tanh.approx.f16x2 %0, %1;" : "=r"(d) : "r"(s));
    return *reinterpret_cast<__half2*>(&d);
}
__device__ __forceinline__ unsigned int h2u(__half2 h) {
    return *reinterpret_cast<unsigned int*>(&h);
}
__device__ __forceinline__ unsigned int packh2(float lo, float hi) {
    return h2u(__floats2half2_rn(lo, hi));
}
__device__ __forceinline__ void mma16816(float* d,
                                         const unsigned* a,
                                         unsigned b0, unsigned b1,
                                         const float* c) {
    asm volatile(
        "mma.sync.aligned.m16n8k16.row.col.f32.f16.f16.f32 "
        "{%0,%1,%2,%3}, {%4,%5,%6,%7}, {%8,%9}, {%10,%11,%12,%13};"
        : "=f"(d[0]), "=f"(d[1]), "=f"(d[2]), "=f"(d[3])
        : "r"(a[0]), "r"(a[1]), "r"(a[2]), "r"(a[3]),
          "r"(b0), "r"(b1),
          "f"(c[0]), "f"(c[1]), "f"(c[2]), "f"(c[3]));
}
__device__ __forceinline__ unsigned int prmt(unsigned int a, unsigned int b,
                                             unsigned int c) {
    unsigned int d;
    asm("prmt.b32 %0, %1, %2, %3;" : "=r"(d) : "r"(a), "r"(b), "r"(c));
    return d;
}

__global__ void __launch_bounds__(32, 1)
gru_kernel(const float* __restrict__ x,
           const float* __restrict__ w_ih,
           const float* __restrict__ w_hh,
           const float* __restrict__ b_ih,
           const float* __restrict__ b_hh,
           const float* __restrict__ head_w,
           const float* __restrict__ head_b,
           float* __restrict__ out,
           int B, int T)
{
    const int b0  = blockIdx.x * 16;        // sixteen batches per warp
    const int tid = threadIdx.x;
    const int gid = tid >> 2;               // 0..7
    const int tig = tid & 3;                // 0..3

    // x chunk buffer: [chunk parity][t 0..31][batch 0..15] halves
    __shared__ __align__(16) __half xbuf[2][32][16];

    // ---- A fragments: W_hh stationary (r,z scaled 0.5), shared by streams.
    unsigned int a[6][2][4];
    #pragma unroll
    for (int t = 0; t < 6; t++) {
        const float s = (t < 4) ? 0.5f : 1.0f;
        #pragma unroll
        for (int kt = 0; kt < 2; kt++) {
            const int r0 = 16 * t + gid, r1 = r0 + 8;
            const int c  = 16 * kt + 2 * tig;
            a[t][kt][0] = packh2(w_hh[r0 * 32 + c] * s,     w_hh[r0 * 32 + c + 1] * s);
            a[t][kt][1] = packh2(w_hh[r1 * 32 + c] * s,     w_hh[r1 * 32 + c + 1] * s);
            a[t][kt][2] = packh2(w_hh[r0 * 32 + c + 8] * s, w_hh[r0 * 32 + c + 9] * s);
            a[t][kt][3] = packh2(w_hh[r1 * 32 + c + 8] * s, w_hh[r1 * 32 + c + 9] * s);
        }
    }

    // ---- C initializers: bias per row (same for all batch cols).
    float cinit[6][4];
    #pragma unroll
    for (int t = 0; t < 6; t++) {
        const int r0 = 16 * t + gid, r1 = r0 + 8;
        float v0, v1;
        if (t < 4) { v0 = 0.5f * (b_ih[r0] + b_hh[r0]);
                     v1 = 0.5f * (b_ih[r1] + b_hh[r1]); }
        else       { v0 = b_hh[r0]; v1 = b_hh[r1]; }
        cinit[t][0] = v0; cinit[t][1] = v0;
        cinit[t][2] = v1; cinit[t][3] = v1;
    }

    // ---- tail constants per owned unit u = gid + 8j
    __half2 wir2[4], wiz2[4], win2[4], cnx2[4];
    #pragma unroll
    for (int j = 0; j < 4; j++) {
        const int u = gid + 8 * j;
        wir2[j] = __float2half2_rn(w_ih[u]      * 0.5f);
        wiz2[j] = __float2half2_rn(w_ih[32 + u] * 0.5f);
        win2[j] = __float2half2_rn(w_ih[64 + u]);
        cnx2[j] = __float2half2_rn(b_ih[64 + u]);
    }
    const __half2 hlf2 = __float2half2_rn(0.5f);

    // ---- B-fragment rebuild constants (same for both streams)
    const int srcA = 8 * tig + (gid >> 1);
    const int srcB = srcA + 4;
    const unsigned int pctl = (gid & 1) ? 0x7632u : 0x5410u;

    // ---- state: two streams, 4 packed units each
    __half2 hS[2][4];
    #pragma unroll
    for (int s = 0; s < 2; s++)
        #pragma unroll
        for (int j = 0; j < 4; j++) hS[s][j] = __float2half2_rn(0.0f);

    // ---- x pipeline: lane covers t-offset tid, all 16 batches
    const float* xb = x + (long long)b0 * T;
    float xv[16];
    #pragma unroll
    for (int b = 0; b < 16; b++) xv[b] = xb[b * T + tid];

    for (int t0 = 0; t0 < T; t0 += 32) {
        const int cp = (t0 >> 5) & 1;
        {
            uint4 p0, p1;
            p0.x = packh2(xv[0],  xv[1]);   p0.y = packh2(xv[2],  xv[3]);
            p0.z = packh2(xv[4],  xv[5]);   p0.w = packh2(xv[6],  xv[7]);
            p1.x = packh2(xv[8],  xv[9]);   p1.y = packh2(xv[10], xv[11]);
            p1.z = packh2(xv[12], xv[13]);  p1.w = packh2(xv[14], xv[15]);
            *reinterpret_cast<uint4*>(&xbuf[cp][tid][0]) = p0;
            *reinterpret_cast<uint4*>(&xbuf[cp][tid][8]) = p1;
        }
        asm volatile("" ::: "memory");
        {
            const int tn = (t0 + 32 < T) ? (t0 + 32) : t0;
            #pragma unroll
            for (int b = 0; b < 16; b++) xv[b] = xb[b * T + tn + tid];
        }

        for (int k = 0; k < 32; k++) {
            // x for this step, per stream, batches {2tig, 2tig+1}
            __half2 xtS[2];
            xtS[0] = *reinterpret_cast<const __half2*>(&xbuf[cp][k][2 * tig]);
            xtS[1] = *reinterpret_cast<const __half2*>(&xbuf[cp][k][8 + 2 * tig]);

            // ---- rebuild B fragments for both streams ----
            unsigned int bb[2][4];
            #pragma unroll
            for (int s = 0; s < 2; s++) {
                #pragma unroll
                for (int j = 0; j < 4; j++) {
                    unsigned int hu = h2u(hS[s][j]);
                    bb[s][j] = prmt(__shfl_sync(FULL_MASK, hu, srcA),
                                    __shfl_sync(FULL_MASK, hu, srcB), pctl);
                }
            }

            // ---- 12 HMMA per stream, interleaved (independent chains) ----
            float d0[6][4], d1[6][4];
            #pragma unroll
            for (int t = 0; t < 6; t++) {
                mma16816(d0[t], a[t][0], bb[0][0], bb[0][1], cinit[t]);
                mma16816(d1[t], a[t][0], bb[1][0], bb[1][1], cinit[t]);
            }
            #pragma unroll
            for (int t = 0; t < 6; t++) {
                mma16816(d0[t], a[t][1], bb[0][2], bb[0][3], d0[t]);
                mma16816(d1[t], a[t][1], bb[1][2], bb[1][3], d1[t]);
            }

            // ---- gate tails, both streams ----
            #pragma unroll
            for (int s = 0; s < 2; s++) {
                float (*d)[4] = (s == 0) ? d0 : d1;
                __half2 xt2 = xtS[s];
                #pragma unroll
                for (int j = 0; j < 4; j++) {
                    const int ts  = (j >= 2) ? 1 : 0;
                    const int off = (j & 1) ? 2 : 0;
                    __half2 hr2 = __floats2half2_rn(d[ts][off],     d[ts][off + 1]);
                    __half2 hz2 = __floats2half2_rn(d[2 + ts][off], d[2 + ts][off + 1]);
                    __half2 hn2 = __floats2half2_rn(d[4 + ts][off], d[4 + ts][off + 1]);

                    __half2 pre_r = __hfma2(xt2, wir2[j], hr2);
                    __half2 pre_z = __hfma2(xt2, wiz2[j], hz2);
                    __half2 rg = __hfma2(htanh2(pre_r), hlf2, hlf2);
                    __half2 zg = __hfma2(htanh2(pre_z), hlf2, hlf2);
                    __half2 xn2 = __hfma2(xt2, win2[j], cnx2[j]);
                    __half2 ng = htanh2(__hfma2(rg, hn2, xn2));
                    hS[s][j] = __hfma2(zg, __hsub2(hS[s][j], ng), ng);
                }
            }
        }
    }

    // ---- head, per stream ----
    #pragma unroll
    for (int s = 0; s < 2; s++) {
        float pA0 = 0.f, pA1 = 0.f, pB0 = 0.f, pB1 = 0.f;
        #pragma unroll
        for (int j = 0; j < 4; j++) {
            const int u = gid + 8 * j;
            float2 hf = __half22float2(hS[s][j]);
            float w0 = head_w[u], w1 = head_w[32 + u];
            pA0 += hf.x * w0;  pA1 += hf.x * w1;
            pB0 += hf.y * w0;  pB1 += hf.y * w1;
        }
        #pragma unroll
        for (int m = 4; m <= 16; m <<= 1) {
            pA0 += __shfl_xor_sync(FULL_MASK, pA0, m);
            pA1 += __shfl_xor_sync(FULL_MASK, pA1, m);
            pB0 += __shfl_xor_sync(FULL_MASK, pB0, m);
            pB1 += __shfl_xor_sync(FULL_MASK, pB1, m);
        }
        if (gid == 0) {                      // tid 0..3 (= tig)
            const int ba = b0 + 8 * s + 2 * tig;
            out[ba * 2]           = pA0 + head_b[0];
            out[ba * 2 + 1]       = pA1 + head_b[1];
            out[(ba + 1) * 2]     = pB0 + head_b[0];
            out[(ba + 1) * 2 + 1] = pB1 + head_b[1];
        }
    }
}

extern "C" void kernel_launch(void* const* d_in, const int* in_sizes, int n_in,
                              void* d_out, int out_size) {
    const float* x      = (const float*)d_in[0];
    const float* w_ih   = (const float*)d_in[1];
    const float* w_hh   = (const float*)d_in[2];
    const float* b_ih   = (const float*)d_in[3];
    const float* b_hh   = (const float*)d_in[4];
    const float* head_w = (const float*)d_in[5];
    const float* head_b = (const float*)d_in[6];
    float* out = (float*)d_out;

    const int B = out_size / 2;           // 2048
    const int T = in_sizes[0] / B;        // 2048

    gru_kernel<<<B / 16, 32>>>(x, w_ih, w_hh, b_ih, b_hh, head_w, head_b, out, B, T);
}

// round 17
// speedup vs baseline: 1.4900x; 1.4900x over previous
#include <cuda_runtime.h>
#include <cuda_fp16.h>

// SimpleGRU: B=2048, T=2048, H=32, scalar input.
// R17: tensor cores with SWAPPED operand roles — batches on M (A = h,
// dynamic), W_hh^T stationary on B, f16 accumulate, biases in f16 C.
// The D output (f16) is preacts packed as unit-pair half2 per thread,
// and the tail's h_new half2 ARE the next step's A-fragment registers:
// the recurrence stays entirely in registers — no shfl, no prmt, no cvt.
// One warp = 8 batches (m rows 8..15 are don't-care), grid 256.
// Thread map: gid = tid>>2 = batch slot; tig = tid&3; thread owns
// unit-pairs {8q+2tig, 8q+2tig+1}, q = 0..3, of its batch.

#define FULL_MASK 0xffffffffu

__device__ __forceinline__ __half2 htanh2(__half2 a) {
    unsigned int d, s = *reinterpret_cast<unsigned int*>(&a);
    asm("tanh.approx.f16x2 %0, %1;" : "=r"(d) : "r"(s));
    return *reinterpret_cast<__half2*>(&d);
}
__device__ __forceinline__ __half2 u2h(unsigned int u) {
    return *reinterpret_cast<const __half2*>(&u);
}
__device__ __forceinline__ unsigned int h2u(__half2 h) {
    return *reinterpret_cast<unsigned int*>(&h);
}
__device__ __forceinline__ unsigned int packh2(float lo, float hi) {
    return h2u(__floats2half2_rn(lo, hi));
}
// m16n8k16 row.col, f16 D/A/B/C. D regs: {d0, d1}.
__device__ __forceinline__ void mma16816_f16(unsigned& d0, unsigned& d1,
                                             unsigned a0, unsigned a1,
                                             unsigned a2, unsigned a3,
                                             unsigned b0, unsigned b1,
                                             unsigned c0, unsigned c1) {
    asm volatile(
        "mma.sync.aligned.m16n8k16.row.col.f16.f16.f16.f16 "
        "{%0,%1}, {%2,%3,%4,%5}, {%6,%7}, {%8,%9};"
        : "=r"(d0), "=r"(d1)
        : "r"(a0), "r"(a1), "r"(a2), "r"(a3),
          "r"(b0), "r"(b1), "r"(c0), "r"(c1));
}

__global__ void __launch_bounds__(32, 1)
gru_kernel(const float* __restrict__ x,
           const float* __restrict__ w_ih,
           const float* __restrict__ w_hh,
           const float* __restrict__ b_ih,
           const float* __restrict__ b_hh,
           const float* __restrict__ head_w,
           const float* __restrict__ head_b,
           float* __restrict__ out,
           int B, int T)
{
    const int bb  = blockIdx.x * 8;         // eight batches per warp
    const int tid = threadIdx.x;
    const int gid = tid >> 2;               // batch slot 0..7
    const int tig = tid & 3;

    // x chunk buffer: [parity][t 0..31][batch 0..7] halves
    __shared__ __align__(16) __half xbuf[2][32][8];

    // ---- B fragments: W_hh^T stationary.
    // n-tile nt covers W rows 8nt..8nt+7 (nt 0-3: r, 4-7: z, 8-11: n);
    // k-tile kt covers units 16kt..16kt+15. r,z rows scaled by 0.5.
    // b0 = {W[8nt+gid][16kt+2tig], [..+1]}, b1 = {.. +8, +9}.
    unsigned wb[12][2][2];
    #pragma unroll
    for (int nt = 0; nt < 12; nt++) {
        const float s = (nt < 8) ? 0.5f : 1.0f;
        const float* Wr = w_hh + (8 * nt + gid) * 32;
        #pragma unroll
        for (int kt = 0; kt < 2; kt++) {
            const int c = 16 * kt + 2 * tig;
            wb[nt][kt][0] = packh2(Wr[c] * s,     Wr[c + 1] * s);
            wb[nt][kt][1] = packh2(Wr[c + 8] * s, Wr[c + 9] * s);
        }
    }

    // ---- C bias fragments (vary along n = W rows; constant along m).
    // c0 = {bias[8nt+2tig], bias[8nt+2tig+1]}. r,z: 0.5*(b_ih+b_hh); n: b_hh.
    unsigned cb[12];
    #pragma unroll
    for (int nt = 0; nt < 12; nt++) {
        const int r0 = 8 * nt + 2 * tig;
        float v0, v1;
        if (nt < 8) { v0 = 0.5f * (b_ih[r0] + b_hh[r0]);
                      v1 = 0.5f * (b_ih[r0 + 1] + b_hh[r0 + 1]); }
        else        { v0 = b_hh[r0]; v1 = b_hh[r0 + 1]; }
        cb[nt] = packh2(v0, v1);
    }

    // ---- tail constants per unit-pair q: units {8q+2tig, 8q+2tig+1}
    __half2 wir2[4], wiz2[4], win2[4], cnx2[4];
    #pragma unroll
    for (int q = 0; q < 4; q++) {
        const int u = 8 * q + 2 * tig;
        wir2[q] = __floats2half2_rn(w_ih[u] * 0.5f,      w_ih[u + 1] * 0.5f);
        wiz2[q] = __floats2half2_rn(w_ih[32 + u] * 0.5f, w_ih[33 + u] * 0.5f);
        win2[q] = __floats2half2_rn(w_ih[64 + u],        w_ih[65 + u]);
        cnx2[q] = __floats2half2_rn(b_ih[64 + u],        b_ih[65 + u]);
    }
    const __half2 hlf2 = __float2half2_rn(0.5f);

    // ---- state: h[batch gid][unit-pair q] as half2 == next A fragments.
    __half2 h2[4];
    #pragma unroll
    for (int q = 0; q < 4; q++) h2[q] = __float2half2_rn(0.0f);

    // ---- x pipeline: lane covers t-offset tid, all 8 batches.
    const float* xb = x + (long long)bb * T;
    float xv[8];
    #pragma unroll
    for (int b = 0; b < 8; b++) xv[b] = xb[b * T + tid];

    for (int t0 = 0; t0 < T; t0 += 32) {
        const int cp = (t0 >> 5) & 1;
        {
            uint4 pk;
            pk.x = packh2(xv[0], xv[1]);  pk.y = packh2(xv[2], xv[3]);
            pk.z = packh2(xv[4], xv[5]);  pk.w = packh2(xv[6], xv[7]);
            *reinterpret_cast<uint4*>(&xbuf[cp][tid][0]) = pk;
        }
        asm volatile("" ::: "memory");  // convergent warp; parity kills WAR
        {
            const int tn = (t0 + 32 < T) ? (t0 + 32) : t0;
            #pragma unroll
            for (int b = 0; b < 8; b++) xv[b] = xb[b * T + tn + tid];
        }

        for (int k = 0; k < 32; k++) {
            // x for this thread's batch, broadcast to both halves.
            __half2 xt2 = __half2half2(xbuf[cp][k][gid]);

            // A fragments from state (rows gid+8 are don't-care -> dummies).
            const unsigned a0 = h2u(h2[0]), a1 = h2u(h2[1]);
            const unsigned a2 = h2u(h2[2]), a3 = h2u(h2[3]);

            // 24 HMMA (12 n-tiles x 2 chained k-tiles), f16 accumulate.
            unsigned d[12], dg[12];
            #pragma unroll
            for (int nt = 0; nt < 12; nt++)
                mma16816_f16(d[nt], dg[nt],
                             a0, a0, a1, a1,
                             wb[nt][0][0], wb[nt][0][1],
                             cb[nt], cb[nt]);
            #pragma unroll
            for (int nt = 0; nt < 12; nt++)
                mma16816_f16(d[nt], dg[nt],
                             a2, a2, a3, a3,
                             wb[nt][1][0], wb[nt][1][1],
                             d[nt], dg[nt]);

            // Tail: 4 unit-pairs, preacts straight from D (no cvt).
            #pragma unroll
            for (int q = 0; q < 4; q++) {
                __half2 dr = u2h(d[q]);          // 0.5*(r-preact) - x-side
                __half2 dz = u2h(d[4 + q]);
                __half2 dn = u2h(d[8 + q]);      // h-side n + b_hh_n

                __half2 pre_r = __hfma2(xt2, wir2[q], dr);
                __half2 pre_z = __hfma2(xt2, wiz2[q], dz);
                __half2 rg = __hfma2(htanh2(pre_r), hlf2, hlf2);   // sigmoid
                __half2 zg = __hfma2(htanh2(pre_z), hlf2, hlf2);
                __half2 xn2 = __hfma2(xt2, win2[q], cnx2[q]);
                __half2 ng = htanh2(__hfma2(rg, dn, xn2));
                h2[q] = __hfma2(zg, __hsub2(h2[q], ng), ng);
            }
        }
    }

    // ---- head: out[b][o] = sum_u h[u][b]*head_w[o][u] + head_b[o] ----
    float p0 = 0.f, p1 = 0.f;
    #pragma unroll
    for (int q = 0; q < 4; q++) {
        const int u = 8 * q + 2 * tig;
        float2 hf = __half22float2(h2[q]);
        p0 += hf.x * head_w[u]      + hf.y * head_w[u + 1];
        p1 += hf.x * head_w[32 + u] + hf.y * head_w[33 + u];
    }
    // reduce across the 4 lanes sharing this batch (xor low 2 bits).
    #pragma unroll
    for (int m = 1; m <= 2; m <<= 1) {
        p0 += __shfl_xor_sync(FULL_MASK, p0, m);
        p1 += __shfl_xor_sync(FULL_MASK, p1, m);
    }
    if (tig == 0) {
        out[2 * (bb + gid)]     = p0 + head_b[0];
        out[2 * (bb + gid) + 1] = p1 + head_b[1];
    }
}

extern "C" void kernel_launch(void* const* d_in, const int* in_sizes, int n_in,
                              void* d_out, int out_size) {
    const float* x      = (const float*)d_in[0];
    const float* w_ih   = (const float*)d_in[1];
    const float* w_hh   = (const float*)d_in[2];
    const float* b_ih   = (const float*)d_in[3];
    const float* b_hh   = (const float*)d_in[4];
    const float* head_w = (const float*)d_in[5];
    const float* head_b = (const float*)d_in[6];
    float* out = (float*)d_out;

    const int B = out_size / 2;           // 2048
    const int T = in_sizes[0] / B;        // 2048

    gru_kernel<<<B / 8, 32>>>(x, w_ih, w_hh, b_ih, b_hh, head_w, head_b, out, B, T);
}